// round 5
// baseline (speedup 1.0000x reference)
#include <cuda_runtime.h>
#include <cuda_bf16.h>

// PointLayerNorm, R5: segment-aligned chunking so the norm pass re-reads x
// from L2 instead of DRAM (L2 persists across launches; only L1 flushes).
// 8 chunks of 4 segments: per chunk, reduce(chunk) then norm(chunk).

#define Bc 4
#define Nc 200000
#define Cc 96
#define C4 (Cc / 4)          // 24 float4 per point
#define Sc 32
#define KEYS (Bc * Sc)
#define EPSF 1e-5f
#define SPC 4                // segments per chunk
#define NCHUNKS (Sc / SPC)   // 8

__device__ float g_sum[KEYS];
__device__ float g_sumsq[KEYS];

__global__ void pln_zero_kernel() {
    int i = threadIdx.x;
    if (i < KEYS) { g_sum[i] = 0.f; g_sumsq[i] = 0.f; }
}

__device__ __forceinline__ void flush_key(int key, float& sA, float& sB,
                                          float& s2A, float& s2B, int lane) {
    float s = sA + sB, s2 = s2A + s2B;
    #pragma unroll
    for (int o = 16; o; o >>= 1) {
        s  += __shfl_xor_sync(0xffffffffu, s,  o);
        s2 += __shfl_xor_sync(0xffffffffu, s2, o);
    }
    if (lane == 0) {
        atomicAdd(&g_sum[key],   s);
        atomicAdd(&g_sumsq[key], s2);
    }
    sA = sB = s2A = s2B = 0.f;
}

// Reduce one chunk: points n in [offs[s0], offs[s0+SPC]) for all 4 batches,
// linearized as q in [0, 4*pts). Warp-contiguous ranges; 8-point groups with
// 6 LDG.128 per lane (MLP 6); key flush only on segment/batch change.
__global__ __launch_bounds__(256) void pln_reduce_chunk(
    const float4* __restrict__ x4, const int* __restrict__ idx,
    const int* __restrict__ offs, int s0)
{
    int n0  = __ldg(&offs[s0]);
    int n1  = __ldg(&offs[s0 + SPC]);
    int pts = n1 - n0;
    int Q   = Bc * pts;

    int wid    = (blockIdx.x * blockDim.x + threadIdx.x) >> 5;
    int lane   = threadIdx.x & 31;
    int totalW = (gridDim.x * blockDim.x) >> 5;
    int chunk  = (((Q + totalW - 1) / totalW) + 7) & ~7;
    int q0 = wid * chunk;
    int q1 = min(q0 + chunk, Q);
    if (q0 >= q1) return;

    int b = q0 / pts;
    int n = n0 + (q0 - b * pts);

    float sA = 0.f, sB = 0.f, s2A = 0.f, s2B = 0.f;
    int curKey = -1;

    int q = q0;
    while (q < q1) {
        bool full = (q + 8 <= q1) && (n + 8 <= n1);
        if (full) {
            int kl = 0;
            if (lane < 8) kl = (b * Sc + __ldg(&idx[n + lane])) & (KEYS - 1);
            int k0 = __shfl_sync(0xffffffffu, kl, 0);
            bool uni = __all_sync(0xffffffffu, lane >= 8 || kl == k0);
            if (uni) {
                if (k0 != curKey) {
                    if (curKey >= 0) flush_key(curKey, sA, sB, s2A, s2B, lane);
                    curKey = k0;
                }
                const float4* base = x4 + (size_t)(b * Nc + n) * C4;
                float4 v0 = __ldg(base + lane);
                float4 v1 = __ldg(base + lane + 32);
                float4 v2 = __ldg(base + lane + 64);
                float4 v3 = __ldg(base + lane + 96);
                float4 v4 = __ldg(base + lane + 128);
                float4 v5 = __ldg(base + lane + 160);
                sA += (v0.x + v0.y) + (v0.z + v0.w) + (v2.x + v2.y) + (v2.z + v2.w)
                    + (v4.x + v4.y) + (v4.z + v4.w);
                sB += (v1.x + v1.y) + (v1.z + v1.w) + (v3.x + v3.y) + (v3.z + v3.w)
                    + (v5.x + v5.y) + (v5.z + v5.w);
                s2A = fmaf(v0.x, v0.x, s2A); s2A = fmaf(v0.y, v0.y, s2A);
                s2A = fmaf(v0.z, v0.z, s2A); s2A = fmaf(v0.w, v0.w, s2A);
                s2B = fmaf(v1.x, v1.x, s2B); s2B = fmaf(v1.y, v1.y, s2B);
                s2B = fmaf(v1.z, v1.z, s2B); s2B = fmaf(v1.w, v1.w, s2B);
                s2A = fmaf(v2.x, v2.x, s2A); s2A = fmaf(v2.y, v2.y, s2A);
                s2A = fmaf(v2.z, v2.z, s2A); s2A = fmaf(v2.w, v2.w, s2A);
                s2B = fmaf(v3.x, v3.x, s2B); s2B = fmaf(v3.y, v3.y, s2B);
                s2B = fmaf(v3.z, v3.z, s2B); s2B = fmaf(v3.w, v3.w, s2B);
                s2A = fmaf(v4.x, v4.x, s2A); s2A = fmaf(v4.y, v4.y, s2A);
                s2A = fmaf(v4.z, v4.z, s2A); s2A = fmaf(v4.w, v4.w, s2A);
                s2B = fmaf(v5.x, v5.x, s2B); s2B = fmaf(v5.y, v5.y, s2B);
                s2B = fmaf(v5.z, v5.z, s2B); s2B = fmaf(v5.w, v5.w, s2B);
                q += 8; n += 8;
                if (n >= n1) { n = n0; ++b; }
                continue;
            }
        }
        // Slow path: one point (segment or batch boundary). Warp-uniform.
        {
            int key = (b * Sc + __ldg(&idx[n])) & (KEYS - 1);
            if (key != curKey) {
                if (curKey >= 0) flush_key(curKey, sA, sB, s2A, s2B, lane);
                curKey = key;
            }
            if (lane < C4) {
                float4 v = __ldg(x4 + (size_t)(b * Nc + n) * C4 + lane);
                sA += (v.x + v.y) + (v.z + v.w);
                s2A = fmaf(v.x, v.x, s2A); s2A = fmaf(v.y, v.y, s2A);
                s2A = fmaf(v.z, v.z, s2A); s2A = fmaf(v.w, v.w, s2A);
            }
            ++q; ++n;
            if (n >= n1) { n = n0; ++b; }
        }
    }
    if (curKey >= 0) flush_key(curKey, sA, sB, s2A, s2B, lane);
}

// Normalize one chunk. Finalize folded in: each block computes the chunk's
// 16 (mean, inv) pairs into smem. Division-free hot loop (c4 loop-invariant).
__global__ __launch_bounds__(256) void pln_norm_chunk(
    const float4* __restrict__ x4, const int* __restrict__ idx,
    const int* __restrict__ offs,
    const float4* __restrict__ w4, const float4* __restrict__ b4,
    float4* __restrict__ out4, int s0)
{
    __shared__ float2 s_mi[Bc * SPC];   // [b*SPC + ds] -> (mean, inv_std)
    int n0  = __ldg(&offs[s0]);
    int n1  = __ldg(&offs[s0 + SPC]);
    int pts = n1 - n0;

    if (threadIdx.x < Bc * SPC) {
        int kl = threadIdx.x;
        int bb = kl >> 2, ds = kl & (SPC - 1);
        int seg = s0 + ds;
        float cnt = (float)(__ldg(&offs[seg + 1]) - __ldg(&offs[seg])) * (float)Cc;
        int key = bb * Sc + seg;
        float m   = g_sum[key] / cnt;
        float var = g_sumsq[key] / cnt - m * m;
        s_mi[kl] = make_float2(m, rsqrtf(var + EPSF));
    }
    __syncthreads();

    int T   = gridDim.x * blockDim.x;   // multiple of 24 by launch config
    int tid = blockIdx.x * blockDim.x + threadIdx.x;
    int c4  = tid % C4;
    int dp  = T / C4;
    int nb  = tid / C4;                 // point offset of first element
    float4 wv = __ldg(w4 + c4);
    float4 bv = __ldg(b4 + c4);
    int J = pts * C4;

    #pragma unroll
    for (int bb = 0; bb < Bc; ++bb) {
        size_t ebase = ((size_t)bb * Nc + n0) * C4;
        int n = n0 + nb;
        for (int j = tid; j < J; j += T) {
            int ds = (__ldg(&idx[n]) - s0) & (SPC - 1);
            float2 mi = s_mi[(bb << 2) | ds];
            float4 xv = __ldg(x4 + ebase + j);
            float4 o; float sc, sh;
            sc = mi.y * wv.x; sh = fmaf(-mi.x, sc, bv.x); o.x = fmaf(xv.x, sc, sh);
            sc = mi.y * wv.y; sh = fmaf(-mi.x, sc, bv.y); o.y = fmaf(xv.y, sc, sh);
            sc = mi.y * wv.z; sh = fmaf(-mi.x, sc, bv.z); o.z = fmaf(xv.z, sc, sh);
            sc = mi.y * wv.w; sh = fmaf(-mi.x, sc, bv.w); o.w = fmaf(xv.w, sc, sh);
            out4[ebase + j] = o;
            n += dp;
        }
    }
}

extern "C" void kernel_launch(void* const* d_in, const int* in_sizes, int n_in,
                              void* d_out, int out_size) {
    const float4* x4   = (const float4*)d_in[0];
    const int*    offs = (const int*)d_in[1];
    const int*    idx  = (const int*)d_in[2];
    const float4* w4   = (const float4*)d_in[3];
    const float4* b4   = (const float4*)d_in[4];
    float4* out4 = (float4*)d_out;

    pln_zero_kernel<<<1, 128>>>();
    for (int c = 0; c < NCHUNKS; ++c) {
        int s0 = c * SPC;
        pln_reduce_chunk<<<1024, 256>>>(x4, idx, offs, s0);
        // grid*256 divisible by 24 -> grid divisible by 3.
        pln_norm_chunk<<<1185, 256>>>(x4, idx, offs, w4, b4, out4, s0);
    }
}

// round 6
// speedup vs baseline: 1.3677x; 1.3677x over previous
#include <cuda_runtime.h>
#include <cuda_bf16.h>

// PointLayerNorm, R6: monolithic two-pass (R4 structure; R5 chunking reverted
// — small per-chunk launches ran at 44% DRAM). Reduce upgraded to 8-point
// groups (6x LDG.128, MLP 6, dual accumulator chains). Norm uses streaming
// cache hints (__ldcs/__stcs) for the touch-once x/out streams.

#define Bc 4
#define Nc 200000
#define Cc 96
#define C4 (Cc / 4)            // 24 float4 per point
#define Sc 32
#define KEYS (Bc * Sc)
#define EPSF 1e-5f

__device__ float g_sum[KEYS];
__device__ float g_sumsq[KEYS];
__device__ float4 g_sc[KEYS * C4];   // per (key, c4) scale
__device__ float4 g_sh[KEYS * C4];   // per (key, c4) shift

__global__ void pln_zero_kernel() {
    int i = threadIdx.x;
    if (i < KEYS) { g_sum[i] = 0.f; g_sumsq[i] = 0.f; }
}

__device__ __forceinline__ void flush_key(int key, float& sA, float& sB,
                                          float& s2A, float& s2B, int lane) {
    float s = sA + sB, s2 = s2A + s2B;
    #pragma unroll
    for (int o = 16; o; o >>= 1) {
        s  += __shfl_xor_sync(0xffffffffu, s,  o);
        s2 += __shfl_xor_sync(0xffffffffu, s2, o);
    }
    if (lane == 0) {
        atomicAdd(&g_sum[key],   s);
        atomicAdd(&g_sumsq[key], s2);
    }
    sA = sB = s2A = s2B = 0.f;
}

// One warp owns a contiguous chunk of points (multiple of 8). Fast path: the
// 8 points of a group share one key (true except at ~127 segment boundaries
// + 3 batch seams); lanes read 6 LDG.128 covering 192 consecutive float4s.
__global__ __launch_bounds__(256) void pln_reduce_kernel(
    const float4* __restrict__ x4, const int* __restrict__ idx)
{
    const int P = Bc * Nc;                      // 800000, multiple of 8
    int wid    = (blockIdx.x * blockDim.x + threadIdx.x) >> 5;
    int lane   = threadIdx.x & 31;
    int totalW = (gridDim.x * blockDim.x) >> 5;
    int chunk  = (((P + totalW - 1) / totalW) + 7) & ~7;
    int g0 = wid * chunk;
    int g1 = min(g0 + chunk, P);
    if (g0 >= g1) return;

    float sA = 0.f, sB = 0.f, s2A = 0.f, s2B = 0.f;
    int curKey = -1;

    int g = g0;
    while (g < g1) {
        bool full = (g + 8 <= g1) && ((g % Nc) + 8 <= Nc);
        if (full) {
            int b = g / Nc;
            int n = g - b * Nc;
            int kl = 0;
            if (lane < 8) kl = (b * Sc + __ldg(&idx[n + lane])) & (KEYS - 1);
            int k0 = __shfl_sync(0xffffffffu, kl, 0);
            bool uni = __all_sync(0xffffffffu, lane >= 8 || kl == k0);
            if (uni) {
                if (k0 != curKey) {
                    if (curKey >= 0) flush_key(curKey, sA, sB, s2A, s2B, lane);
                    curKey = k0;
                }
                const float4* base = x4 + (size_t)g * C4;
                float4 v0 = __ldcs(base + lane);
                float4 v1 = __ldcs(base + lane + 32);
                float4 v2 = __ldcs(base + lane + 64);
                float4 v3 = __ldcs(base + lane + 96);
                float4 v4 = __ldcs(base + lane + 128);
                float4 v5 = __ldcs(base + lane + 160);
                sA += (v0.x + v0.y) + (v0.z + v0.w) + (v2.x + v2.y) + (v2.z + v2.w)
                    + (v4.x + v4.y) + (v4.z + v4.w);
                sB += (v1.x + v1.y) + (v1.z + v1.w) + (v3.x + v3.y) + (v3.z + v3.w)
                    + (v5.x + v5.y) + (v5.z + v5.w);
                s2A = fmaf(v0.x, v0.x, s2A); s2A = fmaf(v0.y, v0.y, s2A);
                s2A = fmaf(v0.z, v0.z, s2A); s2A = fmaf(v0.w, v0.w, s2A);
                s2B = fmaf(v1.x, v1.x, s2B); s2B = fmaf(v1.y, v1.y, s2B);
                s2B = fmaf(v1.z, v1.z, s2B); s2B = fmaf(v1.w, v1.w, s2B);
                s2A = fmaf(v2.x, v2.x, s2A); s2A = fmaf(v2.y, v2.y, s2A);
                s2A = fmaf(v2.z, v2.z, s2A); s2A = fmaf(v2.w, v2.w, s2A);
                s2B = fmaf(v3.x, v3.x, s2B); s2B = fmaf(v3.y, v3.y, s2B);
                s2B = fmaf(v3.z, v3.z, s2B); s2B = fmaf(v3.w, v3.w, s2B);
                s2A = fmaf(v4.x, v4.x, s2A); s2A = fmaf(v4.y, v4.y, s2A);
                s2A = fmaf(v4.z, v4.z, s2A); s2A = fmaf(v4.w, v4.w, s2A);
                s2B = fmaf(v5.x, v5.x, s2B); s2B = fmaf(v5.y, v5.y, s2B);
                s2B = fmaf(v5.z, v5.z, s2B); s2B = fmaf(v5.w, v5.w, s2B);
                g += 8;
                continue;
            }
        }
        // Slow path: one point (segment or batch boundary). Warp-uniform.
        {
            int b = g / Nc;
            int n = g - b * Nc;
            int key = (b * Sc + __ldg(&idx[n])) & (KEYS - 1);
            if (key != curKey) {
                if (curKey >= 0) flush_key(curKey, sA, sB, s2A, s2B, lane);
                curKey = key;
            }
            if (lane < C4) {
                float4 v = __ldcs(x4 + (size_t)g * C4 + lane);
                sA += (v.x + v.y) + (v.z + v.w);
                s2A = fmaf(v.x, v.x, s2A); s2A = fmaf(v.y, v.y, s2A);
                s2A = fmaf(v.z, v.z, s2A); s2A = fmaf(v.w, v.w, s2A);
            }
            ++g;
        }
    }
    if (curKey >= 0) flush_key(curKey, sA, sB, s2A, s2B, lane);
}

// Per-(key, c4) scale/shift tables: o = x * sc + sh.
__global__ void pln_finalize_kernel(const int* __restrict__ offs,
                                    const float4* __restrict__ w4,
                                    const float4* __restrict__ b4)
{
    int i = blockIdx.x * blockDim.x + threadIdx.x;
    if (i < KEYS * C4) {
        int k  = i / C4;
        int c4 = i - k * C4;
        int seg = k & (Sc - 1);
        float cnt = (float)(offs[seg + 1] - offs[seg]) * (float)Cc;
        float m   = g_sum[k] / cnt;
        float var = g_sumsq[k] / cnt - m * m;
        float iv  = rsqrtf(var + EPSF);
        float4 wv = __ldg(w4 + c4);
        float4 bv = __ldg(b4 + c4);
        float4 sc, sh;
        sc.x = iv * wv.x; sh.x = fmaf(-m, sc.x, bv.x);
        sc.y = iv * wv.y; sh.y = fmaf(-m, sc.y, bv.y);
        sc.z = iv * wv.z; sh.z = fmaf(-m, sc.z, bv.z);
        sc.w = iv * wv.w; sh.w = fmaf(-m, sc.w, bv.w);
        g_sc[i] = sc;
        g_sh[i] = sh;
    }
}

// Division-free: total threads T is a multiple of C4, so each thread's c4 is
// loop-invariant and its point index advances by dp = T/C4 per iteration.
// x/out are touch-once -> streaming loads/stores keep L2 for the tables.
__global__ __launch_bounds__(256) void pln_norm_kernel(
    const float4* __restrict__ x4, const int* __restrict__ idx,
    float4* __restrict__ out4)
{
    const int P = Bc * Nc;
    const int E = P * C4;                      // 19,200,000 float4s
    int T   = gridDim.x * blockDim.x;          // multiple of 24 by launch config
    int tid = blockIdx.x * blockDim.x + threadIdx.x;
    int dp  = T / C4;

    int p  = tid / C4;
    int c4 = tid - p * C4;
    int b  = p / Nc;
    int n  = p - b * Nc;

    for (int e = tid; e < E; e += T) {
        int key = (b * Sc + __ldg(&idx[n])) & (KEYS - 1);
        int t   = key * C4 + c4;
        float4 sc = g_sc[t];
        float4 sh = g_sh[t];
        float4 xv = __ldcs(x4 + e);
        float4 o;
        o.x = fmaf(xv.x, sc.x, sh.x);
        o.y = fmaf(xv.y, sc.y, sh.y);
        o.z = fmaf(xv.z, sc.z, sh.z);
        o.w = fmaf(xv.w, sc.w, sh.w);
        __stcs(out4 + e, o);
        n += dp;
        if (n >= Nc) { n -= Nc; ++b; }
    }
}

extern "C" void kernel_launch(void* const* d_in, const int* in_sizes, int n_in,
                              void* d_out, int out_size) {
    const float4* x4   = (const float4*)d_in[0];
    const int*    offs = (const int*)d_in[1];
    const int*    idx  = (const int*)d_in[2];
    const float4* w4   = (const float4*)d_in[3];
    const float4* b4   = (const float4*)d_in[4];
    float4* out4 = (float4*)d_out;

    pln_zero_kernel<<<1, 128>>>();
    pln_reduce_kernel<<<2048, 256>>>(x4, idx);
    pln_finalize_kernel<<<12, 256>>>(offs, w4, b4);
    // grid*256 divisible by 24 -> grid divisible by 3.
    pln_norm_kernel<<<1185, 256>>>(x4, idx, out4);
}